// round 4
// baseline (speedup 1.0000x reference)
#include <cuda_runtime.h>
#include <cstdint>

// ============================================================================
// ScoreNet fused: prep (per-graph) + seg + main MLP (fp32 packed fma.rn.f32x2)
//
// Inputs (metadata order):
//  0 node_attr [N,44] f32      6 w0 [64,128] f32
//  1 t         [B]    f32      7 b0 [64]     f32
//  2 ptr       [B+1]  i32      8 w1 [32,64]  f32
//  3 W_f       [42]   f32      9 b1 [32]     f32
//  4 embed_w   [84,84]f32     10 w2 [4,32]   f32
//  5 embed_b   [84]   f32     11 b2 [4]      f32
// Output: [N,4] f32
// ============================================================================

typedef unsigned long long ull;

#define TPB 256
constexpr int Bg     = 4096;
constexpr int Nn     = 1048576;
constexpr int NTILES = Nn / TPB;   // 4096
constexpr int GRID_MAIN = 592;

__device__ __align__(16) float g_bias0[Bg * 64];
__device__ __align__(16) float g_invstd[Bg];
__device__ __align__(16) int   g_seg[Nn];

// ---------------- main-kernel shared layout (float offsets) ----------------
constexpr int OFF_W0T = 0;                 // [44][64] transposed
constexpr int OFF_W1T = 2816;              // [64][32] transposed
constexpr int OFF_W2T = 4864;              // [32][4]  transposed
constexpr int OFF_B1  = 4992;              // 32
constexpr int OFF_B2  = 5024;              // 4 (+pad)
constexpr int OFF_X   = 5056;              // 256 rows, stride 65
constexpr int XSTRIDE = 65;
constexpr int SMEM_FLOATS = OFF_X + TPB * XSTRIDE;   // 21696
constexpr int SMEM_BYTES  = SMEM_FLOATS * 4;         // 86784 -> 2 blocks/SM

// ---------------- helpers ----------------
__device__ __forceinline__ float swishf(float x) {
    return __fdividef(x, 1.0f + __expf(-x));
}
__device__ __forceinline__ ull dup2(float x) {
    ull r; asm("mov.b64 %0, {%1, %1};" : "=l"(r) : "f"(x)); return r;
}
__device__ __forceinline__ void fma2(ull& acc, ull w, ull x) {
    asm("fma.rn.f32x2 %0, %1, %2, %0;" : "+l"(acc) : "l"(w), "l"(x));
}
__device__ __forceinline__ float2 unpk(ull a) {
    float2 f; asm("mov.b64 {%0, %1}, %2;" : "=f"(f.x), "=f"(f.y) : "l"(a)); return f;
}

// ============================================================================
// Kernel 1: per-graph prep.  128 blocks x 256 threads, 32 graphs per block.
// All weight tables staged in smem once -> no strided global reads.
// ============================================================================
constexpr int GPB       = 32;                 // graphs per block
constexpr int PREP_BLKS = Bg / GPB;           // 128
constexpr int PS_EW   = 0;                    // s_ew  [84][85]
constexpr int PS_W0   = PS_EW + 84 * 85;      // s_w0  [64][85]  (w0[j][44+k])
constexpr int PS_TEMB = PS_W0 + 64 * 85;      // temb  [32][85]
constexpr int PS_EMB  = PS_TEMB + GPB * 85;   // emb   [32][85]
constexpr int PS_T    = PS_EMB + GPB * 85;    // t     [32]
constexpr int PREP_FLOATS = PS_T + GPB;
constexpr int PREP_BYTES  = PREP_FLOATS * 4;  // ~72.2 KB

__global__ void prep_kernel(const float* __restrict__ t,
                            const float* __restrict__ Wf,
                            const float* __restrict__ ew,
                            const float* __restrict__ eb,
                            const float* __restrict__ w0,
                            const float* __restrict__ b0)
{
    extern __shared__ float ps[];
    const int tid = threadIdx.x;
    const int g0  = blockIdx.x * GPB;

    // stage ew [84][84] coalesced -> padded rows
    for (int idx = tid; idx < 84 * 84; idx += TPB) {
        int j = idx / 84, k = idx - j * 84;
        ps[PS_EW + j * 85 + k] = ew[idx];
    }
    // stage w0[:,44:128) -> [j][k], k<84
    for (int idx = tid; idx < 64 * 84; idx += TPB) {
        int j = idx / 84, k = idx - j * 84;
        ps[PS_W0 + j * 85 + k] = w0[j * 128 + 44 + k];
    }
    if (tid < GPB) ps[PS_T + tid] = t[g0 + tid];
    __syncthreads();

    // temb: 32 graphs x 42 freqs -> sin/cos
    for (int idx = tid; idx < GPB * 42; idx += TPB) {
        int g = idx / 42, k = idx - g * 42;
        float p = ps[PS_T + g] * Wf[k] * 6.283185307179586f;
        ps[PS_TEMB + g * 85 + k]      = sinf(p);
        ps[PS_TEMB + g * 85 + 42 + k] = cosf(p);
    }
    __syncthreads();

    // emb: 32 x 84 outputs, each 84-MAC from smem
    for (int idx = tid; idx < GPB * 84; idx += TPB) {
        int g = idx / 84, j = idx - g * 84;
        float acc = eb[j];
        const float* tb = ps + PS_TEMB + g * 85;
        const float* wr = ps + PS_EW + j * 85;
        #pragma unroll 4
        for (int k = 0; k < 84; k++) acc += tb[k] * wr[k];
        ps[PS_EMB + g * 85 + j] = swishf(acc);
    }
    __syncthreads();

    // bias0: 32 x 64 outputs, each 84-MAC; coalesced global write
    for (int idx = tid; idx < GPB * 64; idx += TPB) {
        int g = idx >> 6, j = idx & 63;
        float acc = b0[j];
        const float* eb_ = ps + PS_EMB + g * 85;
        const float* wr  = ps + PS_W0 + j * 85;
        #pragma unroll 4
        for (int k = 0; k < 84; k++) acc += eb_[k] * wr[k];
        g_bias0[(g0 + g) * 64 + j] = acc;
    }
    if (tid < GPB) {
        const float ls = 3.2188758248682006f;  // ln 25
        float var = expm1f(2.0f * ps[PS_T + tid] * ls) / (2.0f * ls);
        g_invstd[g0 + tid] = rsqrtf(var);
    }
}

// ============================================================================
// Kernel 2: seg[i] = searchsorted(ptr, i, 'right') - 1
// ============================================================================
__global__ void seg_kernel(const int* __restrict__ ptr)
{
    const int node = blockIdx.x * blockDim.x + threadIdx.x;
    int lo = 0, hi = Bg;
    #pragma unroll
    for (int it = 0; it < 13; it++) {
        if (lo < hi) {
            int mid = (lo + hi + 1) >> 1;
            if (ptr[mid] <= node) lo = mid; else hi = mid - 1;
        }
    }
    g_seg[node] = lo;
}

// ============================================================================
// Kernel 3: main MLP.  256 threads / 256-node tile.
// Thread t: idx = t&127, jh = t>>7.  Handles nodes (idx, idx+128) for the
// jh-th half of the output dim (layers 0/1).  Two threads share each node
// row, so every layer is strictly read-phase -> __syncthreads() -> write-
// phase (accumulators are in registers across the barrier).  This is the
// race fix for R2.
// ============================================================================
__global__ __launch_bounds__(TPB, 2)
void main_mlp(const float* __restrict__ node_attr,
              const float* __restrict__ w0,
              const float* __restrict__ w1,
              const float* __restrict__ b1,
              const float* __restrict__ w2,
              const float* __restrict__ b2,
              float* __restrict__ out)
{
    extern __shared__ float sm[];
    const int tid = threadIdx.x;
    const int idx = tid & 127;
    const int jh  = tid >> 7;

    // ---- stage + transpose weights ----
    float* tmp = sm + OFF_X;
    for (int i = tid; i < 64 * 44; i += TPB) {
        int j = i / 44, k = i - j * 44;
        tmp[i] = w0[j * 128 + k];
    }
    __syncthreads();
    for (int i = tid; i < 44 * 64; i += TPB) {
        int k = i >> 6, j = i & 63;
        sm[OFF_W0T + i] = tmp[j * 44 + k];
    }
    __syncthreads();
    for (int i = tid; i < 2048; i += TPB) tmp[i] = w1[i];
    __syncthreads();
    for (int i = tid; i < 2048; i += TPB) {
        int k = i >> 5, j = i & 31;
        sm[OFF_W1T + i] = tmp[j * 64 + k];
    }
    if (tid < 128) { int k = tid >> 2, j = tid & 3; sm[OFF_W2T + tid] = w2[j * 32 + k]; }
    if (tid < 32)  sm[OFF_B1 + tid] = b1[tid];
    if (tid < 4)   sm[OFF_B2 + tid] = b2[tid];

    float* xa_row = sm + OFF_X + idx * XSTRIDE;          // node idx
    float* xb_row = xa_row + 128 * XSTRIDE;              // node idx+128
    float* xs_row = sm + OFF_X + tid * XSTRIDE;          // own node (layer 2)

    for (int tile = blockIdx.x; tile < NTILES; tile += gridDim.x) {
        __syncthreads();   // prior tile's layer-2 readers done / weight scratch done

        // ---- stage 256 x 44 coalesced float4 into stride-65 rows ----
        const float4* gx = (const float4*)(node_attr + (size_t)tile * TPB * 44);
        #pragma unroll
        for (int it = 0; it < 11; it++) {
            int i = it * TPB + tid;
            float4 v = gx[i];
            int l = i / 11, kk = (i - l * 11) * 4;
            float* d = sm + OFF_X + l * XSTRIDE + kk;
            d[0] = v.x; d[1] = v.y; d[2] = v.z; d[3] = v.w;
        }
        __syncthreads();

        const int na = tile * TPB + idx;
        const int nb = na + 128;
        const int sa = g_seg[na];
        const int sb = g_seg[nb];

        // ---- layer 0: 44 -> 64, this thread does 32 j's for 2 nodes ----
        ull A[16], Bv[16];
        {
            const ulonglong2* pa = (const ulonglong2*)(g_bias0 + sa * 64 + jh * 32);
            const ulonglong2* pb = (const ulonglong2*)(g_bias0 + sb * 64 + jh * 32);
            #pragma unroll
            for (int i = 0; i < 8; i++) {
                ulonglong2 va = pa[i]; A[2*i] = va.x; A[2*i+1] = va.y;
                ulonglong2 vb = pb[i]; Bv[2*i] = vb.x; Bv[2*i+1] = vb.y;
            }
        }
        #pragma unroll 4
        for (int k = 0; k < 44; k++) {
            ull xa = dup2(xa_row[k]);
            ull xb = dup2(xb_row[k]);
            const ulonglong2* wp = (const ulonglong2*)(sm + OFF_W0T + k * 64 + jh * 32);
            #pragma unroll
            for (int i = 0; i < 8; i++) {
                ulonglong2 w = wp[i];
                fma2(A[2*i],    w.x, xa);
                fma2(A[2*i+1],  w.y, xa);
                fma2(Bv[2*i],   w.x, xb);
                fma2(Bv[2*i+1], w.y, xb);
            }
        }
        __syncthreads();   // RACE FIX: all x reads complete before h0 overwrites rows
        {
            float* da = xa_row + jh * 32;
            float* db = xb_row + jh * 32;
            #pragma unroll
            for (int i = 0; i < 16; i++) {
                float2 fa = unpk(A[i]);  da[2*i] = swishf(fa.x); da[2*i+1] = swishf(fa.y);
                float2 fb = unpk(Bv[i]); db[2*i] = swishf(fb.x); db[2*i+1] = swishf(fb.y);
            }
        }
        __syncthreads();

        // ---- layer 1: 64 -> 32, this thread does 16 j's for 2 nodes ----
        {
            const ulonglong2* bp = (const ulonglong2*)(sm + OFF_B1 + jh * 16);
            #pragma unroll
            for (int i = 0; i < 4; i++) {
                ulonglong2 v = bp[i];
                A[2*i]  = v.x; A[2*i+1]  = v.y;
                Bv[2*i] = v.x; Bv[2*i+1] = v.y;
            }
        }
        #pragma unroll 4
        for (int k = 0; k < 64; k++) {
            ull xa = dup2(xa_row[k]);
            ull xb = dup2(xb_row[k]);
            const ulonglong2* wp = (const ulonglong2*)(sm + OFF_W1T + k * 32 + jh * 16);
            #pragma unroll
            for (int i = 0; i < 4; i++) {
                ulonglong2 w = wp[i];
                fma2(A[2*i],    w.x, xa);
                fma2(A[2*i+1],  w.y, xa);
                fma2(Bv[2*i],   w.x, xb);
                fma2(Bv[2*i+1], w.y, xb);
            }
        }
        __syncthreads();   // RACE FIX: all h0 reads complete before h1 overwrites rows
        {
            float* da = xa_row + jh * 16;
            float* db = xb_row + jh * 16;
            #pragma unroll
            for (int i = 0; i < 8; i++) {
                float2 fa = unpk(A[i]);  da[2*i] = swishf(fa.x); da[2*i+1] = swishf(fa.y);
                float2 fb = unpk(Bv[i]); db[2*i] = swishf(fb.x); db[2*i+1] = swishf(fb.y);
            }
        }
        __syncthreads();

        // ---- layer 2: 32 -> 4 for own node, scale, store ----
        const int ns   = tile * TPB + tid;
        const float invstd = g_invstd[g_seg[ns]];
        ull c0, c1;
        { ulonglong2 v = *(const ulonglong2*)(sm + OFF_B2); c0 = v.x; c1 = v.y; }
        #pragma unroll 8
        for (int k = 0; k < 32; k++) {
            ull xx = dup2(xs_row[k]);
            ulonglong2 w = *(const ulonglong2*)(sm + OFF_W2T + k * 4);
            fma2(c0, w.x, xx);
            fma2(c1, w.y, xx);
        }
        float2 o01 = unpk(c0), o23 = unpk(c1);
        float4 o;
        o.x = swishf(o01.x) * invstd;
        o.y = swishf(o01.y) * invstd;
        o.z = swishf(o23.x) * invstd;
        o.w = swishf(o23.y) * invstd;
        *(float4*)(out + (size_t)ns * 4) = o;
    }
}

// ============================================================================
extern "C" void kernel_launch(void* const* d_in, const int* in_sizes, int n_in,
                              void* d_out, int out_size)
{
    const float* node_attr = (const float*)d_in[0];
    const float* t         = (const float*)d_in[1];
    const int*   ptr       = (const int*)  d_in[2];
    const float* Wf        = (const float*)d_in[3];
    const float* ew        = (const float*)d_in[4];
    const float* eb        = (const float*)d_in[5];
    const float* w0        = (const float*)d_in[6];
    const float* b0        = (const float*)d_in[7];
    const float* w1        = (const float*)d_in[8];
    const float* b1        = (const float*)d_in[9];
    const float* w2        = (const float*)d_in[10];
    const float* b2        = (const float*)d_in[11];
    float* out = (float*)d_out;

    cudaFuncSetAttribute(main_mlp,    cudaFuncAttributeMaxDynamicSharedMemorySize, SMEM_BYTES);
    cudaFuncSetAttribute(prep_kernel, cudaFuncAttributeMaxDynamicSharedMemorySize, PREP_BYTES);

    prep_kernel<<<PREP_BLKS, TPB, PREP_BYTES>>>(t, Wf, ew, eb, w0, b0);
    seg_kernel<<<Nn / TPB, TPB>>>(ptr);
    main_mlp<<<GRID_MAIN, TPB, SMEM_BYTES>>>(node_attr, w0, w1, b1, w2, b2, out);
}

// round 11
// speedup vs baseline: 1.7449x; 1.7449x over previous
// Bisect build: R8 mma pipeline with cp.async/XS staging REMOVED (direct
// global reads) and smem reduced 112640->90112 (2 CTA/SM = 176KB << 227KB).
#include <cuda_runtime.h>
#include <cuda_bf16.h>
#include <cstdint>

typedef unsigned long long ull;

constexpr int Bg = 4096, Nn = 1048576;
constexpr int TILES = Nn / 128;
constexpr int MGRID = 296;

__device__ __align__(16) float g_bias0[Bg * 64];
__device__ __align__(16) float g_invstd[Bg];
__device__ __align__(16) int   g_seg[Nn];
__device__ __align__(16) char  g_wtab[24576];   // [0,16384) W0cat, [16384,24576) W1cat

// ---------------- helpers ----------------
__device__ __forceinline__ uint32_t smem_u32(const void* p) {
    uint32_t a;
    asm("{ .reg .u64 t; cvta.to.shared.u64 t, %1; cvt.u32.u64 %0, t; }" : "=r"(a) : "l"(p));
    return a;
}
__device__ __forceinline__ void ldsm4(uint32_t* r, uint32_t a) {
    asm volatile("ldmatrix.sync.aligned.m8n8.x4.shared.b16 {%0,%1,%2,%3}, [%4];"
        : "=r"(r[0]), "=r"(r[1]), "=r"(r[2]), "=r"(r[3]) : "r"(a));
}
__device__ __forceinline__ void ldsm2(uint32_t* r, uint32_t a) {
    asm volatile("ldmatrix.sync.aligned.m8n8.x2.shared.b16 {%0,%1}, [%2];"
        : "=r"(r[0]), "=r"(r[1]) : "r"(a));
}
__device__ __forceinline__ void mma16816(float* c, const uint32_t* a, const uint32_t* b) {
    asm volatile("mma.sync.aligned.m16n8k16.row.col.f32.bf16.bf16.f32 "
        "{%0,%1,%2,%3}, {%4,%5,%6,%7}, {%8,%9}, {%0,%1,%2,%3};"
        : "+f"(c[0]), "+f"(c[1]), "+f"(c[2]), "+f"(c[3])
        : "r"(a[0]), "r"(a[1]), "r"(a[2]), "r"(a[3]), "r"(b[0]), "r"(b[1]));
}
__device__ __forceinline__ void sts32(uint32_t a, uint32_t v) {
    asm volatile("st.shared.b32 [%0], %1;" :: "r"(a), "r"(v) : "memory");
}
__device__ __forceinline__ void sts64(uint32_t a, uint32_t x, uint32_t y) {
    asm volatile("st.shared.v2.b32 [%0], {%1,%2};" :: "r"(a), "r"(x), "r"(y) : "memory");
}

__device__ __forceinline__ float swishN(float x) {
    float e = __expf(-fmaxf(x, -30.0f));
    float d = 1.0f + e;
    float r = __uint_as_float(0x7EF311C3u - __float_as_uint(d));
    r = r * (2.0f - d * r);
    r = r * (2.0f - d * r);
    return x * r;
}
__device__ __forceinline__ uint32_t bf2(float lo, float hi) {   // low half <- lo
    uint32_t r;
    asm("cvt.rn.satfinite.bf16x2.f32 %0, %1, %2;" : "=r"(r) : "f"(hi), "f"(lo));
    return r;
}
__device__ __forceinline__ float bflo(uint32_t p) { return __uint_as_float(p << 16); }
__device__ __forceinline__ float bfhi(uint32_t p) { return __uint_as_float(p & 0xFFFF0000u); }
__device__ __forceinline__ ull pk2(float x, float y) {
    ull r; asm("mov.b64 %0, {%1, %2};" : "=l"(r) : "f"(x), "f"(y)); return r;
}
__device__ __forceinline__ ull dup2(float x) { ull r; asm("mov.b64 %0, {%1, %1};" : "=l"(r) : "f"(x)); return r; }
__device__ __forceinline__ void fma2(ull& a, ull w, ull x) { asm("fma.rn.f32x2 %0, %1, %2, %0;" : "+l"(a) : "l"(w), "l"(x)); }
__device__ __forceinline__ ull add2(ull a, ull b) { ull r; asm("add.rn.f32x2 %0, %1, %2;" : "=l"(r) : "l"(a), "l"(b)); return r; }
__device__ __forceinline__ float2 unpk(ull a) { float2 f; asm("mov.b64 {%0, %1}, %2;" : "=f"(f.x), "=f"(f.y) : "l"(a)); return f; }
__device__ __forceinline__ ull shflx2(ull v, int d) {
    uint32_t lo = (uint32_t)v, hi = (uint32_t)(v >> 32);
    lo = __shfl_xor_sync(0xffffffffu, lo, d);
    hi = __shfl_xor_sync(0xffffffffu, hi, d);
    return ((ull)hi << 32) | lo;
}

// ============================================================================
// pack: W0cat [64 j][96 kk] = [W0hi(44)|0(4)|W0lo(44)|0(4)], pitch 256B,
//       W1cat [32 j][128 kk] = [W1hi(64)|W1lo(64)], pitch 256B.
// XOR-16B swizzle (group' = group ^ (j&7)); pitch 256 = 16 groups => closed.
// ============================================================================
__global__ void pack_kernel(const float* __restrict__ w0, const float* __restrict__ w1)
{
    int idx = blockIdx.x * blockDim.x + threadIdx.x;
    if (idx < 64 * 96) {
        int j = idx / 96, kk = idx - j * 96;
        float o = 0.0f;
        if (kk < 44) o = __bfloat162float(__float2bfloat16_rn(w0[j * 128 + kk]));
        else if (kk >= 48 && kk < 92) {
            float v = w0[j * 128 + kk - 48];
            o = v - __bfloat162float(__float2bfloat16_rn(v));
        }
        uint32_t b = j * 256 + (((kk >> 3) ^ (j & 7)) << 4) + (kk & 7) * 2;
        *(__nv_bfloat16*)(g_wtab + b) = __float2bfloat16_rn(o);
    } else if (idx < 64 * 96 + 32 * 128) {
        int i2 = idx - 64 * 96;
        int j = i2 >> 7, kk = i2 & 127;
        float v, o;
        if (kk < 64) { v = w1[j * 64 + kk]; o = __bfloat162float(__float2bfloat16_rn(v)); }
        else { v = w1[j * 64 + kk - 64]; o = v - __bfloat162float(__float2bfloat16_rn(v)); }
        uint32_t b = 16384 + j * 256 + (((kk >> 3) ^ (j & 7)) << 4) + (kk & 7) * 2;
        *(__nv_bfloat16*)(g_wtab + b) = __float2bfloat16_rn(o);
    }
}

// ============================================================================
// prep: per-graph bias0 + invstd
// ============================================================================
constexpr int GPB = 16, PREP_BLKS = Bg / GPB;
constexpr int PS_EW = 0, PS_W0 = 84 * 88, PS_TEMB = PS_W0 + 64 * 88,
              PS_EMB = PS_TEMB + GPB * 88, PS_T = PS_EMB + GPB * 88;
constexpr int PREP_BYTES = (PS_T + GPB) * 4;

__global__ void prep_kernel(const float* __restrict__ t,  const float* __restrict__ Wf,
                            const float* __restrict__ ew, const float* __restrict__ eb,
                            const float* __restrict__ w0, const float* __restrict__ b0)
{
    extern __shared__ float ps[];
    const int tid = threadIdx.x;
    const int g0  = blockIdx.x * GPB;
    for (int i = tid; i < 84 * 84; i += 256) { int j = i / 84, k = i - j * 84; ps[PS_EW + j * 88 + k] = ew[i]; }
    for (int i = tid; i < 64 * 84; i += 256) { int j = i / 84, k = i - j * 84; ps[PS_W0 + j * 88 + k] = w0[j * 128 + 44 + k]; }
    if (tid < GPB) ps[PS_T + tid] = t[g0 + tid];
    __syncthreads();
    for (int i = tid; i < GPB * 42; i += 256) {
        int g = i / 42, k = i - g * 42;
        float p = ps[PS_T + g] * Wf[k] * 6.283185307179586f;
        ps[PS_TEMB + g * 88 + k]      = sinf(p);
        ps[PS_TEMB + g * 88 + 42 + k] = cosf(p);
    }
    __syncthreads();
    for (int i = tid; i < GPB * 84; i += 256) {
        int g = i / 84, j = i - g * 84;
        float acc = eb[j];
        const float4* tb = (const float4*)(ps + PS_TEMB + g * 88);
        const float4* wr = (const float4*)(ps + PS_EW + j * 88);
        #pragma unroll
        for (int k = 0; k < 21; k++) { float4 a = tb[k], b = wr[k]; acc += a.x*b.x + a.y*b.y + a.z*b.z + a.w*b.w; }
        ps[PS_EMB + g * 88 + j] = __fdividef(acc, 1.0f + __expf(-acc));
    }
    __syncthreads();
    for (int i = tid; i < GPB * 64; i += 256) {
        int g = i >> 6, j = i & 63;
        float acc = b0[j];
        const float4* em = (const float4*)(ps + PS_EMB + g * 88);
        const float4* wr = (const float4*)(ps + PS_W0 + j * 88);
        #pragma unroll
        for (int k = 0; k < 21; k++) { float4 a = em[k], b = wr[k]; acc += a.x*b.x + a.y*b.y + a.z*b.z + a.w*b.w; }
        g_bias0[(g0 + g) * 64 + j] = acc;
    }
    if (tid < GPB) {
        const float ls = 3.2188758248682006f;  // ln 25
        g_invstd[g0 + tid] = rsqrtf(expm1f(2.0f * ps[PS_T + tid] * ls) / (2.0f * ls));
    }
}

// ============================================================================
// seg: warp-per-graph scatter fill
// ============================================================================
__global__ void seg_kernel(const int* __restrict__ ptr)
{
    int g = blockIdx.x * 8 + (threadIdx.x >> 5);
    if (g >= Bg) return;
    int lo = ptr[g], hi = ptr[g + 1], lane = threadIdx.x & 31;
    for (int i = lo + lane; i < hi; i += 32) g_seg[i] = g;
}

// ============================================================================
// main: bf16 mma.sync L0/L1 (3-term split), f32x2 L2.  Warp-local tiles.
// X read directly from global (no cp.async, no staging buffer).
// ============================================================================
constexpr int SM_W0 = 0, SM_W1 = 16384, SM_XA = 24576, SM_HA = 57344;
constexpr int SMEM_MAIN = 90112;   // 2 CTA/SM = 176KB

__global__ void __launch_bounds__(128, 2)
main_mma(const float* __restrict__ node_attr, const float* __restrict__ w2,
         const float* __restrict__ b1, const float* __restrict__ b2, float* __restrict__ out)
{
    extern __shared__ __align__(16) char sm[];
    const uint32_t smb = smem_u32(sm);
    const int tid = threadIdx.x, w = tid >> 5, lane = tid & 31;
    const int l7 = lane & 7, s3 = (lane >> 3) & 1, s4 = lane >> 4;
    const int c0l = 2 * (lane & 3), rq = lane >> 2;

    { const float4* s = (const float4*)g_wtab; float4* d = (float4*)sm;
      for (int i = tid; i < 1536; i += 128) d[i] = s[i]; }
    __syncthreads();

    ull w2c0[8], w2c1[8]; float b1v[8];
    #pragma unroll
    for (int i = 0; i < 8; i++) {
        int c = (i >> 1) * 8 + c0l + (i & 1);
        w2c0[i] = pk2(w2[c], w2[32 + c]);
        w2c1[i] = pk2(w2[64 + c], w2[96 + c]);
        b1v[i] = b1[c];
    }
    const float b2s = b2[lane & 3];

    const uint32_t xaW = smb + SM_XA + tid * 256;
    const uint32_t aXA0 = smb + SM_XA + (32 * w + (lane & 15)) * 256;
    const uint32_t aXA1 = aXA0 + 16 * 256;
    const uint32_t aHA0 = smb + SM_HA + (32 * w + (lane & 15)) * 256;
    const uint32_t aHA1 = aHA0 + 16 * 256;
    const uint32_t bW0 = smb + SM_W0 + l7 * 256;
    const uint32_t bW1 = smb + SM_W1 + l7 * 256;

    // zero XA pad chunks (cols 44-47 hi -> grp5 hi half, 92-95 lo -> grp11 hi half)
    sts64(xaW + ((5 ^ l7) << 4) + 8, 0u, 0u);
    sts64(xaW + ((11 ^ l7) << 4) + 8, 0u, 0u);

    const int gA0[9]  = {0,2,4,6,8,10,0,2,4};
    const int gB0[9]  = {0,2,4,0,2,4,6,8,10};
    const int gA1[12] = {0,2,4,6,8,10,12,14,0,2,4,6};
    const int gB1[12] = {0,2,4,6,0,2,4,6,8,10,12,14};

    for (int tile = blockIdx.x; tile < TILES; tile += MGRID) {
        // load own X row from global (11 float4), split -> bf16 hi/lo into XA
        {
            const float4* xg = (const float4*)(node_attr + (size_t)(tile * 128 + tid) * 44);
            float4 xv[11];
            #pragma unroll
            for (int q = 0; q < 11; q++) xv[q] = xg[q];
            #pragma unroll
            for (int q = 0; q < 11; q++) {
                float4 v = xv[q];
                uint32_t h0 = bf2(v.x, v.y), h1 = bf2(v.z, v.w);
                uint32_t l0 = bf2(v.x - bflo(h0), v.y - bfhi(h0));
                uint32_t l1 = bf2(v.z - bflo(h1), v.w - bfhi(h1));
                sts64(xaW + (((q >> 1) ^ l7) << 4) + (q & 1) * 8, h0, h1);
                sts64(xaW + ((((q >> 1) + 6) ^ l7) << 4) + (q & 1) * 8, l0, l1);
            }
        }
        __syncwarp();

        // ---- L0 ----
        float acc[2][8][4];
        #pragma unroll
        for (int m = 0; m < 2; m++)
            #pragma unroll
            for (int nb = 0; nb < 8; nb++)
                #pragma unroll
                for (int q = 0; q < 4; q++) acc[m][nb][q] = 0.0f;
        #pragma unroll
        for (int kb = 0; kb < 9; kb++) {
            uint32_t aF0[4], aF1[4];
            ldsm4(aF0, aXA0 + (((gA0[kb] + s4) ^ l7) << 4));
            ldsm4(aF1, aXA1 + (((gA0[kb] + s4) ^ l7) << 4));
            #pragma unroll
            for (int nb = 0; nb < 8; nb++) {
                uint32_t bF[2];
                ldsm2(bF, bW0 + nb * 2048 + (((gB0[kb] + s3) ^ l7) << 4));
                mma16816(acc[0][nb], aF0, bF);
                mma16816(acc[1][nb], aF1, bF);
            }
        }

        // ---- epi0 ----
        const int tb = tile * 128;
        const int r0 = 32 * w + rq;
        const int sg00 = g_seg[tb + r0],      sg01 = g_seg[tb + r0 + 8];
        const int sg10 = g_seg[tb + r0 + 16], sg11 = g_seg[tb + r0 + 24];
        const uint32_t haA = smb + SM_HA + r0 * 256 + c0l * 2;
        #pragma unroll
        for (int m = 0; m < 2; m++) {
            const float* bp0 = g_bias0 + (m ? sg10 : sg00) * 64 + c0l;
            const float* bp1 = g_bias0 + (m ? sg11 : sg01) * 64 + c0l;
            const uint32_t hR0 = haA + m * 16 * 256, hR1 = hR0 + 8 * 256;
            #pragma unroll
            for (int nb = 0; nb < 8; nb++) {
                float2 bv0 = *(const float2*)(bp0 + nb * 8);
                float2 bv1 = *(const float2*)(bp1 + nb * 8);
                float h00 = swishN(acc[m][nb][0] + bv0.x), h01 = swishN(acc[m][nb][1] + bv0.y);
                float h10 = swishN(acc[m][nb][2] + bv1.x), h11 = swishN(acc[m][nb][3] + bv1.y);
                uint32_t p0 = bf2(h00, h01), p1 = bf2(h10, h11);
                uint32_t q0 = bf2(h00 - bflo(p0), h01 - bfhi(p0));
                uint32_t q1 = bf2(h10 - bflo(p1), h11 - bfhi(p1));
                sts32(hR0 + ((nb ^ rq) << 4), p0);
                sts32(hR1 + ((nb ^ rq) << 4), p1);
                sts32(hR0 + (((8 + nb) ^ rq) << 4), q0);
                sts32(hR1 + (((8 + nb) ^ rq) << 4), q1);
            }
        }
        __syncwarp();

        // ---- L1 ----
        float a1[2][4][4];
        #pragma unroll
        for (int m = 0; m < 2; m++)
            #pragma unroll
            for (int nb = 0; nb < 4; nb++)
                #pragma unroll
                for (int q = 0; q < 4; q++) a1[m][nb][q] = 0.0f;
        #pragma unroll
        for (int kb = 0; kb < 12; kb++) {
            uint32_t aF0[4], aF1[4];
            ldsm4(aF0, aHA0 + (((gA1[kb] + s4) ^ l7) << 4));
            ldsm4(aF1, aHA1 + (((gA1[kb] + s4) ^ l7) << 4));
            #pragma unroll
            for (int nb = 0; nb < 4; nb++) {
                uint32_t bF[2];
                ldsm2(bF, bW1 + nb * 2048 + (((gB1[kb] + s3) ^ l7) << 4));
                mma16816(a1[0][nb], aF0, bF);
                mma16816(a1[1][nb], aF1, bF);
            }
        }

        // ---- epi1 ----
        #pragma unroll
        for (int m = 0; m < 2; m++) {
            const int sgr0 = m ? sg10 : sg00, sgr1 = m ? sg11 : sg01;
            const float inv0 = g_invstd[sgr0], inv1 = g_invstd[sgr1];
            ull sA0 = 0, sA1 = 0, sB0 = 0, sB1 = 0;
            #pragma unroll
            for (int i = 0; i < 8; i++) {
                int nb = i >> 1, q = i & 1;
                float hA = swishN(a1[m][nb][q]     + b1v[i]);
                float hB = swishN(a1[m][nb][2 + q] + b1v[i]);
                ull ha = dup2(hA), hb = dup2(hB);
                fma2(sA0, w2c0[i], ha); fma2(sA1, w2c1[i], ha);
                fma2(sB0, w2c0[i], hb); fma2(sB1, w2c1[i], hb);
            }
            sA0 = add2(sA0, shflx2(sA0, 1)); sA0 = add2(sA0, shflx2(sA0, 2));
            sA1 = add2(sA1, shflx2(sA1, 1)); sA1 = add2(sA1, shflx2(sA1, 2));
            sB0 = add2(sB0, shflx2(sB0, 1)); sB0 = add2(sB0, shflx2(sB0, 2));
            sB1 = add2(sB1, shflx2(sB1, 1)); sB1 = add2(sB1, shflx2(sB1, 2));
            float2 fA0 = unpk(sA0), fA1 = unpk(sA1), fB0 = unpk(sB0), fB1 = unpk(sB1);
            float fA = (lane & 2) ? ((lane & 1) ? fA1.y : fA1.x) : ((lane & 1) ? fA0.y : fA0.x);
            float fB = (lane & 2) ? ((lane & 1) ? fB1.y : fB1.x) : ((lane & 1) ? fB0.y : fB0.x);
            const int rA = tb + 32 * w + 16 * m + rq;
            out[(size_t)rA * 4 + (lane & 3)]       = swishN(fA + b2s) * inv0;
            out[(size_t)(rA + 8) * 4 + (lane & 3)] = swishN(fB + b2s) * inv1;
        }
        __syncwarp();
    }
}

// ============================================================================
extern "C" void kernel_launch(void* const* d_in, const int* in_sizes, int n_in,
                              void* d_out, int out_size)
{
    const float* node_attr = (const float*)d_in[0];
    const float* t   = (const float*)d_in[1];
    const int*   ptr = (const int*)  d_in[2];
    const float* Wf  = (const float*)d_in[3];
    const float* ew  = (const float*)d_in[4];
    const float* eb  = (const float*)d_in[5];
    const float* w0  = (const float*)d_in[6];
    const float* b0  = (const float*)d_in[7];
    const float* w1  = (const float*)d_in[8];
    const float* b1  = (const float*)d_in[9];
    const float* w2  = (const float*)d_in[10];
    const float* b2  = (const float*)d_in[11];
    float* out = (float*)d_out;

    cudaFuncSetAttribute(prep_kernel, cudaFuncAttributeMaxDynamicSharedMemorySize, PREP_BYTES);
    cudaFuncSetAttribute(main_mma,    cudaFuncAttributeMaxDynamicSharedMemorySize, SMEM_MAIN);

    pack_kernel<<<40, 256>>>(w0, w1);
    prep_kernel<<<PREP_BLKS, 256, PREP_BYTES>>>(t, Wf, ew, eb, w0, b0);
    seg_kernel<<<512, 256>>>(ptr);
    main_mma<<<MGRID, 128, SMEM_MAIN>>>(node_attr, w2, b1, b2, out);
}